// round 10
// baseline (speedup 1.0000x reference)
#include <cuda_runtime.h>
#include <cuda_bf16.h>
#include <cstdint>

#define K_DIM 1024
#define E_DIM 64
#define NVEC  65536
#define NPIX  4194304
#define KC    64                 // codes per chunk
#define NCH   (K_DIM / KC)       // 16 chunks
#define CAPV  6                  // per-vec near-tie bucket capacity
#define NCTA  (NVEC / 128)       // 512 CTAs

// SMEM layout (bytes)
#define ZT_OFF   0               // z tile  [64 dims][128 vecs] f32      (32 KB)
#define ED_OFF   32768           // dup codebook chunk, i-major, ull     (32 KB)
#define E2S_OFF  65536           // e2 chunk [64] f32
#define Z2S_OFF  65792           // z2 per vec [128] f32
#define KCNT_OFF 66304           // per-vec bucket count [128] int
#define KCAND_OFF 66816          // per-vec bucket [128][CAPV] int (3 KB)
#define SMEM_TOTAL 69888

__device__ double       d_loss_acc;   // zero-init; reset by last CTA each call
__device__ unsigned int d_ticket;
__device__ float        d_e2[K_DIM];
__device__ float        d_cbT[E_DIM * K_DIM];   // transposed codebook [c][k]

typedef unsigned long long ull;

// ---- packed f32x2 helpers ----
__device__ __forceinline__ void fma2(ull& d, ull a, ull b) {
    asm("fma.rn.f32x2 %0, %1, %2, %0;" : "+l"(d) : "l"(a), "l"(b));
}
__device__ __forceinline__ void add2(ull& d, ull a) {
    asm("add.rn.f32x2 %0, %0, %1;" : "+l"(d) : "l"(a));
}
__device__ __forceinline__ float2 unpack2(ull v) {
    float2 r; asm("mov.b64 {%0, %1}, %2;" : "=f"(r.x), "=f"(r.y) : "l"(v)); return r;
}
__device__ __forceinline__ ull pack2(float lo, float hi) {
    ull v; asm("mov.b64 %0, {%1, %2};" : "=l"(v) : "f"(lo), "f"(hi)); return v;
}

// prep: transpose codebook + e2 (float4-sequential, proven rounding structure)
__global__ void prep_kernel(const float* __restrict__ cb) {
    int idx = blockIdx.x * 256 + threadIdx.x;
    if (idx < K_DIM * E_DIM) {
        int c = idx >> 10, k = idx & 1023;
        d_cbT[idx] = cb[k * E_DIM + c];
    }
    if (idx < K_DIM) {
        const float4* r = reinterpret_cast<const float4*>(cb + idx * E_DIM);
        float s = 0.f;
#pragma unroll
        for (int i = 0; i < E_DIM / 4; i++) {
            float4 v = r[i];
            s += v.x * v.x + v.y * v.y + v.z * v.z + v.w * v.w;
        }
        d_e2[idx] = s;
    }
}

// exact distance, bit-identical to the proven round-3 kernel:
// 4-chain f32x2 tree over dim pairs, dot = fadd(lo,hi), dist = fma(-2,dot,fadd(z2,e2)).
__device__ __forceinline__ float exact_dist(const float* zt, int v, float z2,
                                            const float* cb, int k) {
    const ulonglong2* ep = reinterpret_cast<const ulonglong2*>(cb + k * E_DIM);
    ull a0 = 0, a1 = 0, a2 = 0, a3 = 0;
#pragma unroll
    for (int i = 0; i < 8; i++) {
        ulonglong2 e0 = ep[2 * i];
        ulonglong2 e1 = ep[2 * i + 1];
        ull z0 = pack2(zt[(8 * i + 0) * 128 + v], zt[(8 * i + 1) * 128 + v]);
        ull z1 = pack2(zt[(8 * i + 2) * 128 + v], zt[(8 * i + 3) * 128 + v]);
        ull z2p = pack2(zt[(8 * i + 4) * 128 + v], zt[(8 * i + 5) * 128 + v]);
        ull z3 = pack2(zt[(8 * i + 6) * 128 + v], zt[(8 * i + 7) * 128 + v]);
        fma2(a0, z0, e0.x);
        fma2(a1, z1, e0.y);
        fma2(a2, z2p, e1.x);
        fma2(a3, z3, e1.y);
    }
    add2(a0, a1); add2(a2, a3); add2(a0, a2);
    float2 s = unpack2(a0);
    float dot = __fadd_rn(s.x, s.y);
    return __fmaf_rn(-2.0f, dot, __fadd_rn(z2, d_e2[k]));
}

__global__ __launch_bounds__(128, 3)
void vq_kernel(const float* __restrict__ z,
               const float* __restrict__ cb,
               float* __restrict__ out_vq,
               float* __restrict__ out_loss,
               int has_loss) {
    extern __shared__ char sm[];
    float* zt   = reinterpret_cast<float*>(sm + ZT_OFF);
    ull*   ed   = reinterpret_cast<ull*>(sm + ED_OFF);
    float* e2s  = reinterpret_cast<float*>(sm + E2S_OFF);
    float* z2s  = reinterpret_cast<float*>(sm + Z2S_OFF);
    int*   kcnt = reinterpret_cast<int*>(sm + KCNT_OFF);
    int*   kcand = reinterpret_cast<int*>(sm + KCAND_OFF);

    const int tid  = threadIdx.x, lane = tid & 31, w = tid >> 5;
    const int vg   = lane >> 3, cg = lane & 7;       // vec-group / code-group
    const int V0   = w * 32 + vg * 8;                // first of this thread's 8 vecs
    const int m0   = blockIdx.x * 128;
    const int base = (m0 >> 12) * (E_DIM * 4096) + (m0 & 4095);

    // ---- prologue: z tile [dim][vec], bucket counts ----
    for (int idx = tid; idx < E_DIM * 128; idx += 128)
        zt[idx] = z[base + (idx >> 7) * 4096 + (idx & 127)];
    kcnt[tid] = 0;
    __syncthreads();

    // z2 per vec (owner = tid), pair-sequential anchor structure (proven).
    {
        float s = 0.f;
#pragma unroll
        for (int i = 0; i < 32; i++) {
            float lo = zt[(2 * i) * 128 + tid];
            float hi = zt[(2 * i + 1) * 128 + tid];
            s = __fadd_rn(s, __fadd_rn(__fmul_rn(lo, lo), __fmul_rn(hi, hi)));
        }
        z2s[tid] = s;
    }
    __syncthreads();

    float z2r[8];
#pragma unroll
    for (int i = 0; i < 8; i++) z2r[i] = z2s[V0 + i];

    float best[8];
    int   bidx[8];
#pragma unroll
    for (int i = 0; i < 8; i++) { best[i] = 3.4e38f; bidx[i] = 0; }

    // ---- main loop over 16 chunks of 64 codes ----
#pragma unroll 1
    for (int ch = 0; ch < NCH; ch++) {
        const int k0 = ch * KC;
        __syncthreads();
        // load dup'd codebook chunk, i-major conflict-free layout:
        // ed[c*64 + ((kk>>1)&3)*16 + (kk>>3)*2 + (kk&1)] = (e,e)
        for (int idx = tid; idx < E_DIM * KC; idx += 128) {
            int c = idx >> 6, kk = idx & 63;
            float v = d_cbT[c * 1024 + k0 + kk];
            ed[c * 64 + ((kk >> 1) & 3) * 16 + (kk >> 3) * 2 + (kk & 1)] = pack2(v, v);
        }
        if (tid < KC) e2s[tid] = d_e2[k0 + tid];
        __syncthreads();

        ull acc[32];
#pragma unroll
        for (int i = 0; i < 32; i++) acc[i] = 0ull;

#pragma unroll 4
        for (int c = 0; c < E_DIM; c++) {
            const ulonglong2* zp =
                reinterpret_cast<const ulonglong2*>(zt + c * 128 + V0);
            ulonglong2 zA = zp[0];     // vec pairs p0, p1
            ulonglong2 zB = zp[1];     // vec pairs p2, p3
            const ulonglong2* eb = reinterpret_cast<const ulonglong2*>(ed) + c * 32 + cg;
#pragma unroll
            for (int i = 0; i < 4; i++) {
                ulonglong2 e01 = eb[i * 8];   // dup'd codes 2i, 2i+1 for this cg
                fma2(acc[0 * 8 + 2 * i], zA.x, e01.x);
                fma2(acc[1 * 8 + 2 * i], zA.y, e01.x);
                fma2(acc[2 * 8 + 2 * i], zB.x, e01.x);
                fma2(acc[3 * 8 + 2 * i], zB.y, e01.x);
                fma2(acc[0 * 8 + 2 * i + 1], zA.x, e01.y);
                fma2(acc[1 * 8 + 2 * i + 1], zA.y, e01.y);
                fma2(acc[2 * 8 + 2 * i + 1], zB.x, e01.y);
                fma2(acc[3 * 8 + 2 * i + 1], zB.y, e01.y);
            }
        }

        // dist + argmin + near-tie capture (2-ulp window, provably sufficient)
        float eer[8];
#pragma unroll
        for (int j = 0; j < 8; j++) eer[j] = e2s[cg * 8 + j];
#pragma unroll
        for (int j = 0; j < 8; j++) {
            const int kk = k0 + cg * 8 + j;
#pragma unroll
            for (int p = 0; p < 4; p++) {
                float2 d = unpack2(acc[p * 8 + j]);
#pragma unroll
                for (int h = 0; h < 2; h++) {
                    const int vl = 2 * p + h;
                    float dot = h ? d.y : d.x;
                    float da  = __fmaf_rn(-2.0f, dot, __fadd_rn(z2r[vl], eer[j]));
                    int dab = __float_as_int(da);
                    int bb  = __float_as_int(best[vl]);
                    if (da < best[vl]) {
                        if (bb <= dab + 2) {              // old best is a near-tie
                            int s = atomicAdd(&kcnt[V0 + vl], 1);
                            if (s < CAPV) kcand[(V0 + vl) * CAPV + s] = bidx[vl];
                        }
                        best[vl] = da; bidx[vl] = kk;
                    } else if (dab <= bb + 2) {           // near-tie, not better
                        int s = atomicAdd(&kcnt[V0 + vl], 1);
                        if (s < CAPV) kcand[(V0 + vl) * CAPV + s] = kk;
                    }
                }
            }
        }
    }

    // ---- end push: each lane submits its final best if within 2 ulp of group min
#pragma unroll
    for (int i = 0; i < 8; i++) {
        float g = best[i];
#pragma unroll
        for (int o = 1; o < 8; o <<= 1)
            g = fminf(g, __shfl_xor_sync(0xFFFFFFFFu, g, o));
        if (__float_as_int(best[i]) <= __float_as_int(g) + 2) {
            int s = atomicAdd(&kcnt[V0 + i], 1);
            if (s < CAPV) kcand[(V0 + i) * CAPV + s] = bidx[i];
        }
    }
    __syncthreads();

    // ---- owner re-rank (proven exact arithmetic) + epilogue ----
    {
        const int v = tid;
        const float z2v = z2s[v];
        float bestE = 3.4e38f;
        int   bestK = 0;
        int cnt = kcnt[v];
        if (cnt <= CAPV) {
#pragma unroll 1
            for (int s = 0; s < cnt; s++) {
                int k = kcand[v * CAPV + s];
                float de = exact_dist(zt, v, z2v, cb, k);
                if (de < bestE || (de == bestE && k < bestK)) { bestE = de; bestK = k; }
            }
        } else {                         // bucket overflow: full exact scan (rare)
#pragma unroll 1
            for (int k = 0; k < K_DIM; k++) {
                float de = exact_dist(zt, v, z2v, cb, k);
                if (de < bestE) { bestE = de; bestK = k; }
            }
        }

        // gather winner, write vq, loss
        const float2* er = reinterpret_cast<const float2*>(cb + bestK * E_DIM);
        float local = 0.f;
#pragma unroll
        for (int i = 0; i < E_DIM / 2; i++) {
            float2 e = __ldg(&er[i]);
            float p0 = zt[(2 * i) * 128 + v];
            float p1 = zt[(2 * i + 1) * 128 + v];
            float q0 = e.x - p0, q1 = e.y - p1;
            local += q0 * q0 + q1 * q1;
            out_vq[base + (2 * i) * 4096 + v]     = e.x;
            out_vq[base + (2 * i + 1) * 4096 + v] = e.y;
        }
#pragma unroll
        for (int o = 16; o; o >>= 1)
            local += __shfl_xor_sync(0xFFFFFFFFu, local, o);
        if (lane == 0) atomicAdd(&d_loss_acc, (double)local);
    }

    // last-CTA finalize (self-resetting for graph replay)
    __syncthreads();
    if (tid == 0) {
        __threadfence();
        unsigned int done = atomicAdd(&d_ticket, 1u);
        if (done == (unsigned int)(NCTA - 1)) {
            if (has_loss)
                *out_loss = (float)(1.25 * d_loss_acc / (double)NPIX);
            d_loss_acc = 0.0;
            d_ticket   = 0u;
            __threadfence();
        }
    }
}

extern "C" void kernel_launch(void* const* d_in, const int* in_sizes, int n_in,
                              void* d_out, int out_size) {
    const float* z  = (const float*)d_in[0];
    const float* cb = (const float*)d_in[1];
    if (n_in >= 2 && in_sizes[0] == K_DIM * E_DIM && in_sizes[1] == NPIX) {
        const float* t = z; z = cb; cb = t;   // defensive: inputs swapped
    }

    float* out = (float*)d_out;
    int voff = out_size - NPIX;
    if (voff < 0) voff = 0;
    float* out_vq = out + voff;

    cudaFuncSetAttribute(vq_kernel,
                         cudaFuncAttributeMaxDynamicSharedMemorySize, SMEM_TOTAL);

    prep_kernel<<<(K_DIM * E_DIM + 255) / 256, 256>>>(cb);
    vq_kernel<<<NCTA, 128, SMEM_TOTAL>>>(z, cb, out_vq, out, voff > 0 ? 1 : 0);
}

// round 11
// speedup vs baseline: 1.4479x; 1.4479x over previous
#include <cuda_runtime.h>
#include <cuda_bf16.h>

#define K_DIM 1024
#define E_DIM 64
#define NVEC  (16 * 64 * 64)        // 65536 vectors
#define NPIX  (16 * 64 * 64 * 64)   // 4194304 output elements (vq part)
#define KC    128                   // codebook entries per smem chunk
#define NCH   (K_DIM / KC)          // 8 chunks
#define NCTA  (NVEC / 256)          // 256 CTAs, 128 thr, T=2 vectors/thread

// dynamic SMEM layout (bytes)
#define BUF0_OFF 0                  // chunk buffer A: 128x64 f32 (32 KB)
#define BUF1_OFF 32768              // chunk buffer B: 128x64 f32 (32 KB)
#define E2_OFF   65536              // e2 for all 1024 codes (4 KB)
#define SMEM_TOTAL 69632

__device__ double       d_loss_acc;   // zero-init; reset by last CTA each call
__device__ unsigned int d_ticket;     // zero-init; reset by last CTA each call

// ---- packed f32x2 helpers (sm_103a) ----
__device__ __forceinline__ void fma2(unsigned long long& d,
                                     unsigned long long a,
                                     unsigned long long b) {
    asm("fma.rn.f32x2 %0, %1, %2, %0;" : "+l"(d) : "l"(a), "l"(b));
}
__device__ __forceinline__ void add2(unsigned long long& d,
                                     unsigned long long a) {
    asm("add.rn.f32x2 %0, %0, %1;" : "+l"(d) : "l"(a));
}
__device__ __forceinline__ float2 unpack2(unsigned long long v) {
    float2 r;
    asm("mov.b64 {%0, %1}, %2;" : "=f"(r.x), "=f"(r.y) : "l"(v));
    return r;
}
__device__ __forceinline__ unsigned long long pack2(float lo, float hi) {
    unsigned long long v;
    asm("mov.b64 %0, {%1, %2};" : "=l"(v) : "f"(lo), "f"(hi));
    return v;
}

// R7 body (bit-identical arithmetic) + fused e2/finalize + double-buffered
// chunks (one sync per chunk, loads overlapped with the j-loop).
__global__ __launch_bounds__(128, 2)
void vq_kernel(const float* __restrict__ z,
               const float* __restrict__ cb,
               float* __restrict__ out_vq,
               float* __restrict__ out_loss,
               int has_loss) {
    extern __shared__ char sm[];
    float* sh_e2 = reinterpret_cast<float*>(sm + E2_OFF);

    const int tid = threadIdx.x;
    const int n0  = blockIdx.x * 256 + tid;     // vector ids n0 and n0+128
    const int n1  = n0 + 128;
    const int base0 = (n0 >> 12) * (E_DIM * 4096) + (n0 & 4095);
    const int base1 = (n1 >> 12) * (E_DIM * 4096) + (n1 & 4095);

    // Both z rows in registers as packed f32x2.
    unsigned long long zr0[E_DIM / 2], zr1[E_DIM / 2];
#pragma unroll
    for (int i = 0; i < E_DIM / 2; i++) {
        zr0[i] = pack2(z[base0 + (2 * i) * 4096], z[base0 + (2 * i + 1) * 4096]);
        zr1[i] = pack2(z[base1 + (2 * i) * 4096], z[base1 + (2 * i + 1) * 4096]);
    }

    // ||z||^2 fp32, sequential pair order (reference-matching rounding anchor).
    float z20 = 0.f, z21 = 0.f;
#pragma unroll
    for (int i = 0; i < E_DIM / 2; i++) {
        float2 v0 = unpack2(zr0[i]);
        float2 v1 = unpack2(zr1[i]);
        z20 = __fadd_rn(z20, __fadd_rn(__fmul_rn(v0.x, v0.x), __fmul_rn(v0.y, v0.y)));
        z21 = __fadd_rn(z21, __fadd_rn(__fmul_rn(v1.x, v1.x), __fmul_rn(v1.y, v1.y)));
    }

    // e2 for ALL 1024 codes, once (float4-sequential: proven bit-identical).
#pragma unroll
    for (int rr = 0; rr < K_DIM / 128; rr++) {
        int k = rr * 128 + tid;
        const float4* r = reinterpret_cast<const float4*>(cb + k * E_DIM);
        float s = 0.f;
#pragma unroll
        for (int i = 0; i < E_DIM / 4; i++) {
            float4 v = r[i];
            s += v.x * v.x + v.y * v.y + v.z * v.z + v.w * v.w;
        }
        sh_e2[k] = s;
    }

    // Preload chunk 0 into buffer 0.
    {
        const float4* src = reinterpret_cast<const float4*>(cb);
        float4* dst = reinterpret_cast<float4*>(sm + BUF0_OFF);
#pragma unroll
        for (int i = 0; i < (KC * E_DIM / 4) / 128; i++)
            dst[tid + i * 128] = src[tid + i * 128];
    }
    __syncthreads();   // covers chunk0 buffer + sh_e2

    float best0 = 3.4e38f, best1 = 3.4e38f;
    int   bidx0 = 0,       bidx1 = 0;

#pragma unroll 1
    for (int ch = 0; ch < NCH; ch++) {
        const int k0 = ch * KC;
        const float* sh_cb =
            reinterpret_cast<const float*>(sm + ((ch & 1) ? BUF1_OFF : BUF0_OFF));

        // Issue next chunk's load into the other buffer (overlaps the j-loop;
        // safe: that buffer was last read in iteration ch-1, behind the sync).
        if (ch + 1 < NCH) {
            const float4* src =
                reinterpret_cast<const float4*>(cb + (k0 + KC) * E_DIM);
            float4* dst = reinterpret_cast<float4*>(
                sm + ((ch & 1) ? BUF0_OFF : BUF1_OFF));
#pragma unroll
            for (int i = 0; i < (KC * E_DIM / 4) / 128; i++)
                dst[tid + i * 128] = src[tid + i * 128];
        }

#pragma unroll 1
        for (int j = 0; j < KC; j += 2) {
            const ulonglong2* eA =
                reinterpret_cast<const ulonglong2*>(sh_cb + j * E_DIM);
            const ulonglong2* eB =
                reinterpret_cast<const ulonglong2*>(sh_cb + (j + 1) * E_DIM);
            // 16 independent chains (2 vec x 2 codes x 4 chains); per-(vec,code)
            // tree identical to rounds 3/7.
            unsigned long long a0 = 0, a1 = 0, a2 = 0, a3 = 0;   // vec0 x code j
            unsigned long long b0 = 0, b1 = 0, b2 = 0, b3 = 0;   // vec1 x code j
            unsigned long long c0 = 0, c1 = 0, c2 = 0, c3 = 0;   // vec0 x code j+1
            unsigned long long d0 = 0, d1 = 0, d2 = 0, d3 = 0;   // vec1 x code j+1
#pragma unroll
            for (int i = 0; i < 8; i++) {          // 4 LDS.128 + 16 FFMA2 per step
                ulonglong2 xA0 = eA[2 * i];
                ulonglong2 xA1 = eA[2 * i + 1];
                ulonglong2 xB0 = eB[2 * i];
                ulonglong2 xB1 = eB[2 * i + 1];
                fma2(a0, zr0[4 * i + 0], xA0.x);
                fma2(b0, zr1[4 * i + 0], xA0.x);
                fma2(c0, zr0[4 * i + 0], xB0.x);
                fma2(d0, zr1[4 * i + 0], xB0.x);
                fma2(a1, zr0[4 * i + 1], xA0.y);
                fma2(b1, zr1[4 * i + 1], xA0.y);
                fma2(c1, zr0[4 * i + 1], xB0.y);
                fma2(d1, zr1[4 * i + 1], xB0.y);
                fma2(a2, zr0[4 * i + 2], xA1.x);
                fma2(b2, zr1[4 * i + 2], xA1.x);
                fma2(c2, zr0[4 * i + 2], xB1.x);
                fma2(d2, zr1[4 * i + 2], xB1.x);
                fma2(a3, zr0[4 * i + 3], xA1.y);
                fma2(b3, zr1[4 * i + 3], xA1.y);
                fma2(c3, zr0[4 * i + 3], xB1.y);
                fma2(d3, zr1[4 * i + 3], xB1.y);
            }
            add2(a0, a1); add2(a2, a3); add2(a0, a2);
            add2(b0, b1); add2(b2, b3); add2(b0, b2);
            add2(c0, c1); add2(c2, c3); add2(c0, c2);
            add2(d0, d1); add2(d2, d3); add2(d0, d2);
            float2 sA0 = unpack2(a0), sA1 = unpack2(b0);
            float2 sB0 = unpack2(c0), sB1 = unpack2(d0);
            float dotA0 = __fadd_rn(sA0.x, sA0.y);
            float dotA1 = __fadd_rn(sA1.x, sA1.y);
            float dotB0 = __fadd_rn(sB0.x, sB0.y);
            float dotB1 = __fadd_rn(sB1.x, sB1.y);
            float2 e2v = *reinterpret_cast<const float2*>(sh_e2 + k0 + j);
            // Reference fp32 rounding: (z2 + e2) - 2*dot (fma form, exact 2*dot).
            // Code j strictly before j+1: first-occurrence tie-break preserved.
            float dA0 = __fmaf_rn(-2.0f, dotA0, __fadd_rn(z20, e2v.x));
            float dA1 = __fmaf_rn(-2.0f, dotA1, __fadd_rn(z21, e2v.x));
            if (dA0 < best0) { best0 = dA0; bidx0 = k0 + j; }
            if (dA1 < best1) { best1 = dA1; bidx1 = k0 + j; }
            float dB0 = __fmaf_rn(-2.0f, dotB0, __fadd_rn(z20, e2v.y));
            float dB1 = __fmaf_rn(-2.0f, dotB1, __fadd_rn(z21, e2v.y));
            if (dB0 < best0) { best0 = dB0; bidx0 = k0 + j + 1; }
            if (dB1 < best1) { best1 = dB1; bidx1 = k0 + j + 1; }
        }
        __syncthreads();   // next buffer fully written; this buffer free
    }

    // Epilogue: gather winning rows (L2-resident), write vq, accumulate loss.
    float local = 0.f;
    {
        const float2* er = reinterpret_cast<const float2*>(cb + bidx0 * E_DIM);
#pragma unroll
        for (int i = 0; i < E_DIM / 2; i++) {
            float2 e  = __ldg(&er[i]);
            float2 zp = unpack2(zr0[i]);
            float q0 = e.x - zp.x, q1 = e.y - zp.y;
            local += q0 * q0 + q1 * q1;
            out_vq[base0 + (2 * i)     * 4096] = e.x;
            out_vq[base0 + (2 * i + 1) * 4096] = e.y;
        }
    }
    {
        const float2* er = reinterpret_cast<const float2*>(cb + bidx1 * E_DIM);
#pragma unroll
        for (int i = 0; i < E_DIM / 2; i++) {
            float2 e  = __ldg(&er[i]);
            float2 zp = unpack2(zr1[i]);
            float q0 = e.x - zp.x, q1 = e.y - zp.y;
            local += q0 * q0 + q1 * q1;
            out_vq[base1 + (2 * i)     * 4096] = e.x;
            out_vq[base1 + (2 * i + 1) * 4096] = e.y;
        }
    }

    // warp reduce + one double atomic per warp
#pragma unroll
    for (int o = 16; o; o >>= 1)
        local += __shfl_xor_sync(0xFFFFFFFFu, local, o);
    if ((tid & 31) == 0)
        atomicAdd(&d_loss_acc, (double)local);

    // Last-CTA finalize (self-resetting: deterministic across graph replays).
    __syncthreads();
    if (tid == 0) {
        __threadfence();
        unsigned int done = atomicAdd(&d_ticket, 1u);
        if (done == (unsigned int)(NCTA - 1)) {
            if (has_loss)
                *out_loss = (float)(1.25 * d_loss_acc / (double)NPIX);
            d_loss_acc = 0.0;
            d_ticket   = 0u;
            __threadfence();
        }
    }
}

extern "C" void kernel_launch(void* const* d_in, const int* in_sizes, int n_in,
                              void* d_out, int out_size) {
    // metadata order: z [16,64,64,64] fp32, codebook [1024,64] fp32.
    const float* z  = (const float*)d_in[0];
    const float* cb = (const float*)d_in[1];
    if (n_in >= 2 && in_sizes[0] == K_DIM * E_DIM && in_sizes[1] == NPIX) {
        const float* t = z; z = cb; cb = t;   // defensive: inputs swapped
    }

    float* out = (float*)d_out;
    int voff = out_size - NPIX;            // 1 if scalar loss precedes vq_out
    if (voff < 0) voff = 0;
    float* out_vq = out + voff;

    cudaFuncSetAttribute(vq_kernel,
                         cudaFuncAttributeMaxDynamicSharedMemorySize, SMEM_TOTAL);

    vq_kernel<<<NCTA, 128, SMEM_TOTAL>>>(z, cb, out_vq, out, voff > 0 ? 1 : 0);
}